// round 16
// baseline (speedup 1.0000x reference)
#include <cuda_runtime.h>
#include <cstddef>

#define B 16
#define N 1024
#define P 256
#define D 64
#define K 26
#define S 4                 // n-segments (8192 streaming warps - proven optimum)
#define NSEG (N / S)        // 256 n per segment

#define PROD_CTAS 128
#define STREAM_CTAS 2048
#define CTAS_PER_BATCH 128  // 4 segs x 32 p-group CTAs
#define NSLOTS 8            // output n-slots per CTA (1024/128)
#define KD4 (K * D / 4)     // 416 float4 per anchor block

// ---- scratch (no allocations allowed; device globals) ----
__device__ float g_importance[N];            // [n]
__device__ float g_pscore[S * B * P];        // [s, b*P+p] partial scores
__device__ float g_pmean[S * B * P * D];     // [s, b*P+p, d] partial sums
__device__ float g_anchor[B * K * D];        // [b, k, d] finalized anchors
__device__ int   g_done;                     // producer counter
__device__ int   g_cnt[B];                   // per-batch streamer-arrival counters
__device__ int   g_ready[B];                 // per-batch anchor-ready flags
__device__ int   g_fin;                      // retire counter (drives reset)

// ------------------------------------------------------------------
// ONE kernel, four fused phases (each the measured-optimal variant):
//  bid<128: PRODUCER — importance[j]=mean_i adp[i,j], 8 cols/CTA,
//           bump g_done, exit.
//  else:    STREAMER — exact R14 k_main mapping+loop (8192 warps,
//           half-warp per (seg,b,p), contiguous 512B per warp-iter,
//           direct score dot), preceded by a ~2.5us g_done spin.
//           Arrive at g_cnt[b]; the LAST arriver finalizes batch b
//           (fixed-order score reduce -> stable rank-count top-k
//           matching jax.lax.top_k (descending, low index wins ties)
//           -> anchor reduce + 1/N) and sets g_ready[b]. Then all 128
//           CTAs of batch b replicate the anchor block to their 8
//           n-slots with plain write-back stores (measured at LTS cap).
//           2048th retiree resets counters for the next graph replay.
// Slot audit (R15 bugfix): warp rem covers p-pair (rem%128); CTA
// p-group = (rem>>2)&31 (NOT >>3). w = seg*32+pg is a bijection onto
// 0..127 per batch; each CTA writes 8 distinct n-slots -> full cover.
// Deadlock-free: producers wait on nothing and are wave-1 bids;
// ready[b] is set by batch b's last arriver (already running).
// ------------------------------------------------------------------
__global__ void __launch_bounds__(128, 15)
k_all(const float* __restrict__ patches,
      const float* __restrict__ adp,
      float* __restrict__ out) {
    __shared__ float red[16][8];   // producer reduce
    __shared__ float sc[P];        // finalizer: reduced scores
    __shared__ int   tk[K];        // finalizer: top-k indices
    __shared__ int   s_islast;

    int tid = threadIdx.x;
    int bid = blockIdx.x;

    if (bid < PROD_CTAS) {
        // ---------------- producer: 8 columns of adp ----------------
        int jl   = tid & 7;
        int iseg = tid >> 3;             // 0..15, 64 rows each
        int j    = bid * 8 + jl;
        float s = 0.f;
        const float* col = adp + (size_t)(iseg * 64) * N + j;
#pragma unroll 8
        for (int i = 0; i < 64; i++) s += col[(size_t)i * N];
        red[iseg][jl] = s;
        __syncthreads();
        if (tid < 8) {
            float t = 0.f;
#pragma unroll
            for (int r = 0; r < 16; r++) t += red[r][tid];
            g_importance[j - jl + tid] = t * (1.0f / (float)N);
        }
        __threadfence();
        __syncthreads();
        if (tid == 0) atomicAdd(&g_done, 1);
        return;
    }

    // ---------------- streamer (exact R14 k_main mapping) ----------------
    int sid   = bid - PROD_CTAS;                     // 0..2047
    int gwarp = (sid * 128 + tid) >> 5;              // 0 .. S*B*P/2-1
    int lane  = tid & 31;
    int half  = lane >> 4;
    int hl    = lane & 15;

    int seg   = gwarp / (B * (P / 2));               // CTA-uniform
    int rem   = gwarp % (B * (P / 2));
    int b     = rem / (P / 2);                       // CTA-uniform
    int p     = (rem % (P / 2)) * 2 + half;
    int n0    = seg * NSEG;

    // within-batch CTA index (0..127): p-pair group is (rem%128)>>2
    int pg = (rem >> 2) & 31;                        // FIXED (was >>3)
    int w  = seg * 32 + pg;

    // wait for importance (producers are wave-1, finish in ~2.5us)
    if (tid == 0) {
        while (*(volatile int*)&g_done != PROD_CTAS) { __nanosleep(100); }
    }
    __syncthreads();
    __threadfence();                                 // acquire importance

    const float4* base =
        (const float4*)(patches + (((size_t)b * N + n0) * P + p) * (size_t)D) + hl;
    const size_t nstride = (size_t)P * D / 4;        // float4 per n
    const float* imp = g_importance + n0;

    float4 ms = make_float4(0.f, 0.f, 0.f, 0.f);
    float score = 0.f;

#pragma unroll 8
    for (int n = 0; n < NSEG; n++) {
        float4 v = __ldcs(base + (size_t)n * nstride);   // streaming, read-once
        ms.x += v.x; ms.y += v.y; ms.z += v.z; ms.w += v.w;
        float sq = v.x * v.x + v.y * v.y + v.z * v.z + v.w * v.w;
        sq += __shfl_xor_sync(0xffffffffu, sq, 8);
        sq += __shfl_xor_sync(0xffffffffu, sq, 4);
        sq += __shfl_xor_sync(0xffffffffu, sq, 2);
        sq += __shfl_xor_sync(0xffffffffu, sq, 1);
        score += sqrtf(sq) * __ldg(imp + n);
    }

    size_t bp = (size_t)b * P + p;
    ((float4*)g_pmean)[((size_t)seg * B * P + bp) * (D / 4) + hl] = ms;
    if (hl == 0) g_pscore[(size_t)seg * B * P + bp] = score;

    // ---------------- batch arrival + finalizer election ----------------
    __threadfence();                                 // publish partials
    __syncthreads();
    if (tid == 0) {
        int old = atomicAdd(&g_cnt[b], 1);
        s_islast = (old == CTAS_PER_BATCH - 1);
    }
    __syncthreads();

    if (s_islast) {
        __threadfence();                             // acquire batch-b partials
        // 1. score reduce (fixed order -> deterministic)
        for (int pp = tid; pp < P; pp += 128) {
            float v = 0.f;
#pragma unroll
            for (int s = 0; s < S; s++) v += g_pscore[s * B * P + b * P + pp];
            sc[pp] = v;
        }
        __syncthreads();
        // 2. stable rank-count top-k
        for (int pp = tid; pp < P; pp += 128) {
            float my = sc[pp];
            int rank = 0;
#pragma unroll 8
            for (int q = 0; q < P; q++) {
                float v = sc[q];
                rank += (v > my) || (v == my && q < pp);
            }
            if (rank < K) tk[rank] = pp;
        }
        __syncthreads();
        // 3. anchor reduce + 1/N scale
        const int MF4 = B * P * D / 4;
        const float inv = 1.0f / (float)N;
        for (int t = tid; t < KD4; t += 128) {
            int kk  = t >> 4;
            int dd4 = t & 15;
            size_t idx = ((size_t)b * P + tk[kk]) * (D / 4) + dd4;
            float4 a = make_float4(0.f, 0.f, 0.f, 0.f);
#pragma unroll
            for (int s = 0; s < S; s++) {
                float4 v = ((const float4*)g_pmean)[(size_t)s * MF4 + idx];
                a.x += v.x; a.y += v.y; a.z += v.z; a.w += v.w;
            }
            ((float4*)g_anchor)[(size_t)b * KD4 + t] =
                make_float4(a.x * inv, a.y * inv, a.z * inv, a.w * inv);
        }
        __threadfence();
        __syncthreads();
        if (tid == 0) atomicExch(&g_ready[b], 1);
    }

    // ---------------- replicate: 8 n-slots per CTA ----------------
    if (tid == 0) {
        while (*(volatile int*)&g_ready[b] == 0) { __nanosleep(100); }
    }
    __syncthreads();
    __threadfence();                                 // acquire g_anchor[b]

    int t0 = tid, t1 = tid + 128, t2 = tid + 256, t3 = tid + 384;
    const float4* anc = (const float4*)g_anchor + (size_t)b * KD4;
    float4 a0 = anc[t0];
    float4 a1 = anc[t1];
    float4 a2 = anc[t2];
    float4 a3 = (t3 < KD4) ? anc[t3] : make_float4(0, 0, 0, 0);

    float4* obase = (float4*)out + ((size_t)b * N + (size_t)w * NSLOTS) * KD4;
#pragma unroll
    for (int nn = 0; nn < NSLOTS; nn++) {
        float4* o = obase + (size_t)nn * KD4;
        o[t0] = a0;
        o[t1] = a1;
        o[t2] = a2;
        if (t3 < KD4) o[t3] = a3;
    }

    // ---------------- retire + counter reset for next replay ----------------
    __syncthreads();
    if (tid == 0) {
        int o = atomicAdd(&g_fin, 1);
        if (o == STREAM_CTAS - 1) {      // every CTA passed all spins
            g_done = 0;
            g_fin  = 0;
#pragma unroll
            for (int i = 0; i < B; i++) { g_cnt[i] = 0; g_ready[i] = 0; }
            __threadfence();
        }
    }
}

// ------------------------------------------------------------------
extern "C" void kernel_launch(void* const* d_in, const int* in_sizes, int n_in,
                              void* d_out, int out_size) {
    const float* patches = (const float*)d_in[0];
    const float* adp     = (const float*)d_in[1];
    if (n_in >= 2 && in_sizes[0] == N * N && in_sizes[1] == B * N * P * D) {
        const float* t = patches; patches = adp; adp = t;
    }
    float* out = (float*)d_out;

    k_all<<<PROD_CTAS + STREAM_CTAS, 128>>>(patches, adp, out);
}

// round 17
// speedup vs baseline: 1.0541x; 1.0541x over previous
#include <cuda_runtime.h>
#include <cstddef>

#define B 16
#define N 1024
#define P 256
#define D 64
#define K 26
#define S 4                 // n-segments (8192 streaming warps - proven optimum)
#define NSEG (N / S)        // 256 n per segment

#define KD4 (K * D / 4)     // 416 float4 per anchor block

// ---- scratch (no allocations allowed; device globals) ----
__device__ float g_importance[N];            // [n]
__device__ float g_pscore[S * B * P];        // [s, b*P+p] partial scores
__device__ float g_pmean[S * B * P * D];     // [s, b*P+p, d] partial sums
__device__ float g_anchor[B * K * D];        // [b, k, d] finalized anchors

// ------------------------------------------------------------------
// R14's four measured-at-floor kernels, unchanged bodies, chained with
// PDL (programmatic dependent launch): each consumer's grid is
// dispatched while its producer drains; cudaGridDependencySynchronize
// in the prologue guarantees the producer has fully completed before
// dependent data is read.
// ------------------------------------------------------------------

// Kernel 1: importance[j] = mean_i adp[i, j]
// 128 CTAs x 128 thr: 8 cols per CTA (lanes 0..7 -> 32B sectors).
__global__ void __launch_bounds__(128) k_importance(const float* __restrict__ adp) {
    __shared__ float red[16][8];
    int jl   = threadIdx.x & 7;
    int iseg = threadIdx.x >> 3;             // 0..15, 64 rows each
    int j    = blockIdx.x * 8 + jl;

    float s = 0.f;
    const float* col = adp + (size_t)(iseg * 64) * N + j;
#pragma unroll 8
    for (int i = 0; i < 64; i++) s += col[(size_t)i * N];
    red[iseg][jl] = s;
    __syncthreads();
    if (threadIdx.x < 8) {
        float t = 0.f;
#pragma unroll
        for (int r = 0; r < 16; r++) t += red[r][threadIdx.x];
        g_importance[j - jl + threadIdx.x] = t * (1.0f / (float)N);
    }
}

// Kernel 2: the proven-fastest streaming pass (~173us, 6.4 TB/s).
// Half-warp per (seg,b,p); 16 lanes x float4 = d=64; adjacent p per
// warp -> contiguous 512B per warp-iteration; 2048 CTAs = 8192 warps.
__global__ void __launch_bounds__(128) k_main(const float* __restrict__ patches) {
    int gwarp = (blockIdx.x * blockDim.x + threadIdx.x) >> 5;   // 0 .. S*B*P/2-1
    int lane = threadIdx.x & 31;
    int half = lane >> 4;
    int hl   = lane & 15;

    int seg   = gwarp / (B * (P / 2));
    int rem   = gwarp % (B * (P / 2));
    int b     = rem / (P / 2);
    int p     = (rem % (P / 2)) * 2 + half;
    int n0    = seg * NSEG;

    const float4* base =
        (const float4*)(patches + (((size_t)b * N + n0) * P + p) * (size_t)D) + hl;
    const size_t nstride = (size_t)P * D / 4;   // float4 per n
    const float* imp = g_importance + n0;

    // PDL: grid was pre-dispatched; wait for k_importance to complete
    // before reading g_importance. Index math above overlapped the drain.
    cudaGridDependencySynchronize();

    float4 ms = make_float4(0.f, 0.f, 0.f, 0.f);
    float score = 0.f;

#pragma unroll 8
    for (int n = 0; n < NSEG; n++) {
        float4 v = __ldcs(base + (size_t)n * nstride);   // streaming, read-once
        ms.x += v.x; ms.y += v.y; ms.z += v.z; ms.w += v.w;
        float sq = v.x * v.x + v.y * v.y + v.z * v.z + v.w * v.w;
        sq += __shfl_xor_sync(0xffffffffu, sq, 8);
        sq += __shfl_xor_sync(0xffffffffu, sq, 4);
        sq += __shfl_xor_sync(0xffffffffu, sq, 2);
        sq += __shfl_xor_sync(0xffffffffu, sq, 1);
        score += sqrtf(sq) * __ldg(imp + n);
    }

    size_t bp = (size_t)b * P + p;
    ((float4*)g_pmean)[((size_t)seg * B * P + bp) * (D / 4) + hl] = ms;
    if (hl == 0) g_pscore[(size_t)seg * B * P + bp] = score;
}

// Kernel 3: per-batch finalize (16 CTAs x 256 thr, ~3.5us):
// fixed-order score reduce (deterministic) -> stable rank-count top-k
// (matches jax.lax.top_k: descending, lower index wins ties) ->
// anchor reduce + 1/N -> g_anchor[b] (stays L2-hot).
__global__ void __launch_bounds__(256) k_finalize() {
    __shared__ float sc[P];
    __shared__ int   tk[K];
    int b   = blockIdx.x;
    int tid = threadIdx.x;

    cudaGridDependencySynchronize();     // wait for k_main's partials

    {
        float v = 0.f;
#pragma unroll
        for (int s = 0; s < S; s++) v += g_pscore[s * B * P + b * P + tid];
        sc[tid] = v;
    }
    __syncthreads();

    {
        float my = sc[tid];
        int rank = 0;
#pragma unroll 8
        for (int q = 0; q < P; q++) {
            float v = sc[q];
            rank += (v > my) || (v == my && q < tid);
        }
        if (rank < K) tk[rank] = tid;
    }
    __syncthreads();

    const int MF4 = B * P * D / 4;
    const float inv = 1.0f / (float)N;
    for (int t = tid; t < KD4; t += 256) {
        int kk  = t >> 4;
        int dd4 = t & 15;
        size_t idx = ((size_t)b * P + tk[kk]) * (D / 4) + dd4;
        float4 a = make_float4(0.f, 0.f, 0.f, 0.f);
#pragma unroll
        for (int s = 0; s < S; s++) {
            float4 v = ((const float4*)g_pmean)[(size_t)s * MF4 + idx];
            a.x += v.x; a.y += v.y; a.z += v.z; a.w += v.w;
        }
        ((float4*)g_anchor)[(size_t)b * KD4 + t] =
            make_float4(a.x * inv, a.y * inv, a.z * inv, a.w * inv);
    }
}

// Kernel 4: pure replicator (measured at the LTS store cap, ~17.4us).
// Each thread holds <=2 float4 of batch b's anchor block (L2-hot) and
// writes 16 n-replicas with plain write-back stores.
#define NN_PER_BLOCK 16

__global__ void __launch_bounds__(256) k_out(float* __restrict__ out) {
    const int chunks = N / NN_PER_BLOCK;          // 64
    int b = blockIdx.x / chunks;
    int c = blockIdx.x % chunks;
    int tid = threadIdx.x;

    int t0 = tid;
    int t1 = tid + 256;
    float4* obase = (float4*)out + ((size_t)b * N + (size_t)c * NN_PER_BLOCK) * KD4;

    cudaGridDependencySynchronize();     // wait for k_finalize's anchors

    float4 v0 = ((const float4*)g_anchor)[(size_t)b * KD4 + t0];
    float4 v1 = (t1 < KD4) ? ((const float4*)g_anchor)[(size_t)b * KD4 + t1]
                           : make_float4(0, 0, 0, 0);

#pragma unroll
    for (int nn = 0; nn < NN_PER_BLOCK; nn++) {
        float4* o = obase + (size_t)nn * KD4;
        o[t0] = v0;
        if (t1 < KD4) o[t1] = v1;
    }
}

// ------------------------------------------------------------------
template <typename KF, typename... Args>
static inline void launch_pdl(KF kern, dim3 grid, dim3 block, Args... args) {
    cudaLaunchConfig_t cfg = {};
    cfg.gridDim = grid;
    cfg.blockDim = block;
    cfg.dynamicSmemBytes = 0;
    cfg.stream = 0;                      // capture stream (legacy default)
    cudaLaunchAttribute attr[1];
    attr[0].id = cudaLaunchAttributeProgrammaticStreamSerialization;
    attr[0].val.programmaticStreamSerializationAllowed = 1;
    cfg.attrs = attr;
    cfg.numAttrs = 1;
    cudaLaunchKernelEx(&cfg, kern, args...);
}

extern "C" void kernel_launch(void* const* d_in, const int* in_sizes, int n_in,
                              void* d_out, int out_size) {
    const float* patches = (const float*)d_in[0];
    const float* adp     = (const float*)d_in[1];
    if (n_in >= 2 && in_sizes[0] == N * N && in_sizes[1] == B * N * P * D) {
        const float* t = patches; patches = adp; adp = t;
    }
    float* out = (float*)d_out;

    k_importance<<<128, 128>>>(adp);     // head of chain: plain launch
    launch_pdl(k_main,     dim3(S * B * (P / 2) / 4), dim3(128), patches);
    launch_pdl(k_finalize, dim3(B),                   dim3(256));
    launch_pdl(k_out,      dim3(B * (N / NN_PER_BLOCK)), dim3(256), out);
}